// round 14
// baseline (speedup 1.0000x reference)
#include <cuda_runtime.h>
#include <cstddef>
#include <cstdint>
#include <math.h>

#define BB   256
#define VV   50
#define CC   40
#define DD   256
#define HH   256
#define TT   1000

// ---------------- scratch buffer (float offsets) ----------------
constexpr size_t OFF_AB   = 0;            // 1000
constexpr size_t OFF_SA   = 1024;         // 256
constexpr size_t OFF_SB   = 1280;         // 256
constexpr size_t OFF_QP0  = 1536;         // 256
constexpr size_t OFF_CF   = 1792;         // 256
constexpr size_t OFF_BSUM = 2048;         // 1024
constexpr size_t OFF_B2   = 3072;         // 1024
constexpr size_t OFF_MF   = 4096;         // 256*256
constexpr size_t OFF_WOT  = 69632;        // 256*256
constexpr size_t OFF_W2   = 135168;       // 1024*256
constexpr size_t OFF_PK   = 397312;       // 256*256*4 floats (float4-packed w_hh)
constexpr size_t OFF_HID  = 659456;       // 12800*64
constexpr size_t OFF_VE   = 1478656;      // 12800*256
constexpr size_t OFF_G1   = 4755456;      // 12800*256
constexpr size_t OFF_KP   = 8032256;      // 12800*256
constexpr size_t OFF_VP   = 11309056;     // 12800*256
constexpr size_t OFF_O    = 14585856;     // 12800*256 (pre-out-proj attn outputs)
constexpr size_t OFF_XGV  = 17862656;     // 12800*1024
constexpr size_t OFF_XGG  = 30969856;     // 12800*1024
constexpr size_t OFF_H    = 44077056;     // 100*256 (rows 0..49 hv, 50..99 hg)
constexpr size_t OFF_H1   = 44102656;     // 100*1024
constexpr size_t OFF_H2   = 44205056;     // 100*1024
constexpr size_t OFF_PROB = 44307456;     // 100*2
constexpr size_t BUF_SIZE = 44307656;

__device__ float g_buf[BUF_SIZE];

__device__ __forceinline__ float sigf(float x) { return 1.0f / (1.0f + expf(-x)); }

// ---------------- tiny prep kernels ----------------
__global__ void k_ab(const float* __restrict__ betas, float* __restrict__ ab) {
    if (threadIdx.x == 0) {
        float p = 1.0f;
        for (int i = 0; i < TT; i++) { p *= (1.0f - betas[i]); ab[i] = p; }
    }
}

__global__ void k_sab(const int* __restrict__ dt, const float* __restrict__ ab,
                      float* __restrict__ sa, float* __restrict__ sb) {
    int b = threadIdx.x;
    float a = ab[dt[b]];
    sa[b] = sqrtf(a);
    sb[b] = sqrtf(fmaxf(1.0f - a, 0.0f));
}

__global__ void k_prep(const float* __restrict__ wih, const float* __restrict__ bih,
                       const float* __restrict__ bhh, const float* __restrict__ ipw,
                       const float* __restrict__ ipb, const float* __restrict__ opb,
                       float* __restrict__ bsum, float* __restrict__ b2,
                       float* __restrict__ cf, float* __restrict__ qp0) {
    int j = blockIdx.x * 256 + threadIdx.x;
    if (j < 1024) {
        float acc = 0.0f;
        const float* wr = wih + (size_t)j * 256;
        for (int d = 0; d < 256; d++) acc += wr[d] * opb[d];
        bsum[j] = bih[j] + bhh[j];
        b2[j]   = acc + bih[j] + bhh[j];
    } else if (j < 1280) {
        int jj = j - 1024;
        float acc = 0.0f;
        const float* wr = ipw + (size_t)jj * 256;   // Wq row
        for (int d = 0; d < 256; d++) acc += wr[d] * opb[d];
        cf[jj] = acc + ipb[jj];
    } else if (j < 1536) {
        int jj = j - 1280;
        float acc = 0.0f;
        const float* wr = ipw + (size_t)jj * 256;
        for (int d = 0; d < 256; d++) acc += wr[d];
        qp0[jj] = 10000.0f * acc + ipb[jj];
    }
}

__global__ void k_two(const float* __restrict__ wo, float* __restrict__ wot) {
    int e = blockIdx.x, d = threadIdx.x;
    wot[e * 256 + d] = wo[d * 256 + e];     // wot[e,d] = Wo[d,e]
}

__global__ void k_pack(const float* __restrict__ whh, float4* __restrict__ pk) {
    int d = blockIdx.x, j = threadIdx.x;
    pk[d * 256 + j] = make_float4(whh[(0   + j) * 256 + d],
                                  whh[(256 + j) * 256 + d],
                                  whh[(512 + j) * 256 + d],
                                  whh[(768 + j) * 256 + d]);
}

// hid[r*64+k], r = v*256+b
__global__ void k_hid(const float* __restrict__ st, const float* __restrict__ tlw,
                      const float* __restrict__ tlb, float* __restrict__ hid) {
    int gid = blockIdx.x * 256 + threadIdx.x;
    int k = gid & 63;
    int r = gid >> 6;
    int v = r >> 8, b = r & 255;
    float tt = st[b * VV + v] * (1.0f / 180.0f);
    float x = tt * tlw[k] + tlb[k];
    hid[gid] = 1.0f - tanhf(x * x);
}

// ve (tenc already in place) += embedding gather; then gen1
__global__ void k_ve(const int* __restrict__ seqs, const float* __restrict__ emb,
                     const float* __restrict__ nn, const float* __restrict__ pn,
                     const float* __restrict__ sa, const float* __restrict__ sb,
                     float* __restrict__ ve, float* __restrict__ g1) {
    __shared__ int sidx[CC];
    int r = blockIdx.x;
    int d = threadIdx.x;
    int v = r >> 8, b = r & 255;
    if (d < CC) sidx[d] = seqs[(b * VV + v) * CC + d];
    __syncthreads();
    float acc = ve[(size_t)r * 256 + d];   // tenc
#pragma unroll 8
    for (int c = 0; c < CC; c++)
        acc += fmaxf(emb[(size_t)sidx[c] * 256 + d], 0.0f);
    ve[(size_t)r * 256 + d] = acc;
    size_t ni = ((size_t)b * VV + v) * 256 + d;
    g1[(size_t)r * 256 + d] = acc * (1.0f + sa[b]) + nn[ni] * sb[b] - pn[ni];
}

// ---------------- generic tiled SGEMM: C[M,N] = A[M,K] @ B[N,K]^T (+bias)(+relu) --------
__global__ void gemm_nt(const float* __restrict__ A, const float* __restrict__ B,
                        const float* __restrict__ bias, float* __restrict__ C,
                        int M, int N, int K, int relu) {
    __shared__ float As[16 * 68];
    __shared__ float Bs[16 * 68];
    int tid = threadIdx.x;
    int tx = tid & 15, ty = tid >> 4;
    int n0 = blockIdx.x * 64, m0 = blockIdx.y * 64;
    int lr = tid >> 2;            // 0..63
    int lk = (tid & 3) * 4;       // 0,4,8,12
    float acc[4][4] = {};
    for (int k0 = 0; k0 < K; k0 += 16) {
        __syncthreads();
        int ar = m0 + lr;
        float4 av = (ar < M) ? *reinterpret_cast<const float4*>(A + (size_t)ar * K + k0 + lk)
                             : make_float4(0.f, 0.f, 0.f, 0.f);
        float4 bv = *reinterpret_cast<const float4*>(B + (size_t)(n0 + lr) * K + k0 + lk);
        As[(lk + 0) * 68 + lr] = av.x;
        As[(lk + 1) * 68 + lr] = av.y;
        As[(lk + 2) * 68 + lr] = av.z;
        As[(lk + 3) * 68 + lr] = av.w;
        Bs[(lk + 0) * 68 + lr] = bv.x;
        Bs[(lk + 1) * 68 + lr] = bv.y;
        Bs[(lk + 2) * 68 + lr] = bv.z;
        Bs[(lk + 3) * 68 + lr] = bv.w;
        __syncthreads();
#pragma unroll
        for (int kk = 0; kk < 16; kk++) {
            float4 a = *reinterpret_cast<const float4*>(As + kk * 68 + ty * 4);
            float4 b = *reinterpret_cast<const float4*>(Bs + kk * 68 + tx * 4);
            acc[0][0] += a.x * b.x; acc[0][1] += a.x * b.y; acc[0][2] += a.x * b.z; acc[0][3] += a.x * b.w;
            acc[1][0] += a.y * b.x; acc[1][1] += a.y * b.y; acc[1][2] += a.y * b.z; acc[1][3] += a.y * b.w;
            acc[2][0] += a.z * b.x; acc[2][1] += a.z * b.y; acc[2][2] += a.z * b.z; acc[2][3] += a.z * b.w;
            acc[3][0] += a.w * b.x; acc[3][1] += a.w * b.y; acc[3][2] += a.w * b.z; acc[3][3] += a.w * b.w;
        }
    }
#pragma unroll
    for (int i = 0; i < 4; i++) {
        int row = m0 + ty * 4 + i;
        if (row < M) {
#pragma unroll
            for (int j = 0; j < 4; j++) {
                int col = n0 + tx * 4 + j;
                float vout = acc[i][j] + (bias ? bias[col] : 0.0f);
                if (relu) vout = fmaxf(vout, 0.0f);
                C[(size_t)row * N + col] = vout;
            }
        }
    }
}

// ---------------- fused attention step ----------------
// qp_i = O_{i-1} @ M^T + c  (M = Wq@Wo, c = Wq@bo + bq); step0: all q rows = qp0
// scores -> softmax -> O_i = P @ Vp   (O is PRE-out-projection)
#define ATTN_SHM_FLOATS (256*33*2 + 16*256 + 32*257 + 16*32 + 16*256)
#define ATTN_SHM_BYTES  (ATTN_SHM_FLOATS * 4)

__global__ void k_attn(int step, const float* __restrict__ kp, const float* __restrict__ vp,
                       float* __restrict__ O, const float* __restrict__ Mf,
                       const float* __restrict__ cf, const float* __restrict__ qp0) {
    extern __shared__ float sm[];
    float* kps = sm;                    // 256 keys x 32 hd, stride 33
    float* vps = kps + 256 * 33;
    float* oq  = vps + 256 * 33;        // 16 x 256 prev-O rows
    float* Ms  = oq + 16 * 256;         // 32 x 257 M rows for this head
    float* qps = Ms + 32 * 257;         // 16 x 32
    float* ss  = qps + 16 * 32;         // 16 x 256 scores

    int tid = threadIdx.x;
    int head = blockIdx.x, qt = blockIdx.y;
    int q0 = qt * 16;
    const float* kpv = kp + (size_t)step * (BB * DD);
    const float* vpv = vp + (size_t)step * (BB * DD);

    for (int idx = tid; idx < 256 * 32; idx += 256) {
        int k = idx >> 5, hd = idx & 31;
        kps[k * 33 + hd] = kpv[k * 256 + head * 32 + hd];
        vps[k * 33 + hd] = vpv[k * 256 + head * 32 + hd];
    }
    if (step > 0) {
        const float* Op = O + (size_t)(step - 1) * (BB * DD);
        for (int idx = tid; idx < 16 * 256; idx += 256)
            oq[idx] = Op[(q0 + (idx >> 8)) * 256 + (idx & 255)];
        for (int idx = tid; idx < 32 * 256; idx += 256) {
            int j = idx >> 8, e = idx & 255;
            Ms[j * 257 + e] = Mf[(head * 32 + j) * 256 + e];
        }
    }
    __syncthreads();

    int jl = tid & 31, qi = tid >> 5;
    if (step == 0) {
        float vq = qp0[head * 32 + jl];
        qps[qi * 32 + jl] = vq;
        qps[(qi + 8) * 32 + jl] = vq;
    } else {
        for (int qq = qi; qq < 16; qq += 8) {
            float acc = cf[head * 32 + jl];
            const float* orow = oq + qq * 256;
            const float* mrow = Ms + jl * 257;
#pragma unroll 8
            for (int e = 0; e < 256; e++) acc += orow[e] * mrow[e];
            qps[qq * 32 + jl] = acc;
        }
    }
    __syncthreads();

    {   // scores: one key per thread
        int k = tid;
        const float* krow = kps + k * 33;
#pragma unroll
        for (int q = 0; q < 16; q++) {
            const float* qrow = qps + q * 32;
            float acc = 0.0f;
#pragma unroll
            for (int hd = 0; hd < 32; hd++) acc += qrow[hd] * krow[hd];
            ss[q * 256 + k] = acc * 0.17677669529663687f;  // 1/sqrt(32)
        }
    }
    __syncthreads();

    {   // softmax over k; warp w handles q rows w and w+8
        int lane = tid & 31, w = tid >> 5;
        for (int q = w; q < 16; q += 8) {
            float* row = ss + q * 256;
            float vv[8];
            float mx = -1e30f;
#pragma unroll
            for (int m = 0; m < 8; m++) { vv[m] = row[lane + 32 * m]; mx = fmaxf(mx, vv[m]); }
#pragma unroll
            for (int o = 16; o; o >>= 1) mx = fmaxf(mx, __shfl_xor_sync(0xFFFFFFFFu, mx, o));
            float sum = 0.0f;
#pragma unroll
            for (int m = 0; m < 8; m++) { vv[m] = expf(vv[m] - mx); sum += vv[m]; }
#pragma unroll
            for (int o = 16; o; o >>= 1) sum += __shfl_xor_sync(0xFFFFFFFFu, sum, o);
            float inv = 1.0f / sum;
#pragma unroll
            for (int m = 0; m < 8; m++) row[lane + 32 * m] = vv[m] * inv;
        }
    }
    __syncthreads();

    {   // O = P @ Vp
        int hd = tid & 31, qi2 = tid >> 5;
        float* Oo = O + (size_t)step * (BB * DD);
        for (int qq = qi2; qq < 16; qq += 8) {
            const float* prow = ss + qq * 256;
            float acc = 0.0f;
#pragma unroll 8
            for (int k = 0; k < 256; k++) acc += prow[k] * vps[k * 33 + hd];
            Oo[(q0 + qq) * 256 + head * 32 + hd] = acc;
        }
    }
}

// ---------------- LSTM: 50 blocks x 2 chains (ve + gen), 256 sequential steps ----------
__global__ void k_lstm(const float* __restrict__ xgv, const float* __restrict__ xgg,
                       const float4* __restrict__ pk, float* __restrict__ hout) {
    __shared__ float2 hs[256];
    int v = blockIdx.x, tid = threadIdx.x;
    hs[tid] = make_float2(0.0f, 0.0f);
    float c0 = 0.0f, c1 = 0.0f, h0 = 0.0f, h1 = 0.0f;
    const float* x0 = xgv + (size_t)v * 256 * 1024;
    const float* x1 = xgg + (size_t)v * 256 * 1024;
    __syncthreads();
    for (int t = 0; t < 256; t++) {
        const float* a0 = x0 + (size_t)t * 1024;
        const float* a1 = x1 + (size_t)t * 1024;
        float i0 = a0[tid], f0 = a0[tid + 256], g0 = a0[tid + 512], o0 = a0[tid + 768];
        float i1 = a1[tid], f1 = a1[tid + 256], g1 = a1[tid + 512], o1 = a1[tid + 768];
#pragma unroll 4
        for (int d = 0; d < 256; d++) {
            float4 w = pk[d * 256 + tid];
            float2 h = hs[d];
            i0 += w.x * h.x; f0 += w.y * h.x; g0 += w.z * h.x; o0 += w.w * h.x;
            i1 += w.x * h.y; f1 += w.y * h.y; g1 += w.z * h.y; o1 += w.w * h.y;
        }
        c0 = sigf(f0) * c0 + sigf(i0) * tanhf(g0);
        h0 = sigf(o0) * tanhf(c0);
        c1 = sigf(f1) * c1 + sigf(i1) * tanhf(g1);
        h1 = sigf(o1) * tanhf(c1);
        __syncthreads();
        hs[tid] = make_float2(h0, h1);
        __syncthreads();
    }
    hout[v * 256 + tid]        = h0;   // hv rows 0..49
    hout[(VV + v) * 256 + tid] = h1;   // hg rows 50..99
}

// ---------------- logits + softmax over 2 classes ----------------
__global__ void k_logits(const float* __restrict__ h2, const float* __restrict__ cow,
                         const float* __restrict__ cob, float* __restrict__ probs) {
    int t = blockIdx.x * blockDim.x + threadIdx.x;
    if (t >= 100) return;
    const float* hr = h2 + (size_t)t * 1024;
    float l0 = cob[0], l1 = cob[1];
    for (int d = 0; d < 1024; d++) { l0 += hr[d] * cow[d]; l1 += hr[d] * cow[1024 + d]; }
    float m = fmaxf(l0, l1);
    float e0 = expf(l0 - m), e1 = expf(l1 - m);
    float s = e0 + e1;
    probs[t * 2 + 0] = e0 / s;
    probs[t * 2 + 1] = e1 / s;
}

// ---------------- output assembly: first 52224 floats ----------------
__global__ void k_out(const float* __restrict__ probs, float* __restrict__ out) {
    int i = blockIdx.x * 256 + threadIdx.x;
    if (i >= 52224) return;
    float val;
    if (i < 25600) {                       // res [B,V,2]
        int v = (i >> 1) % 50;
        val = probs[v * 2 + (i & 1)];
    } else if (i < 51200) {                // resg [B,V,2]
        int j = i - 25600;
        int v = (j >> 1) % 50;
        val = probs[(50 + v) * 2 + (j & 1)];
    } else if (i < 51712) {                // res[:, -1]
        val = probs[98 + (i & 1)];
    } else {                               // resg[:, -1]
        val = probs[198 + (i & 1)];
    }
    out[i] = val;
}

// ---------------- host launcher ----------------
extern "C" void kernel_launch(void* const* d_in, const int* in_sizes, int n_in,
                              void* d_out, int out_size) {
    (void)in_sizes; (void)n_in; (void)out_size;
    const int*   seqs = (const int*)  d_in[0];
    const float* st   = (const float*)d_in[1];
    const int*   dt   = (const int*)  d_in[2];
    const float* nn   = (const float*)d_in[3];
    const float* pn   = (const float*)d_in[4];
    const float* emb  = (const float*)d_in[5];
    const float* betas= (const float*)d_in[6];
    const float* tlw  = (const float*)d_in[7];
    const float* tlb  = (const float*)d_in[8];
    const float* tuw  = (const float*)d_in[9];
    const float* tub  = (const float*)d_in[10];
    const float* ipw  = (const float*)d_in[11];
    const float* ipb  = (const float*)d_in[12];
    const float* opw  = (const float*)d_in[13];
    const float* opb  = (const float*)d_in[14];
    const float* wih  = (const float*)d_in[15];
    const float* whh  = (const float*)d_in[16];
    const float* bih  = (const float*)d_in[17];
    const float* bhh  = (const float*)d_in[18];
    const float* c1w  = (const float*)d_in[19];
    const float* c1b  = (const float*)d_in[20];
    const float* c2w  = (const float*)d_in[21];
    const float* c2b  = (const float*)d_in[22];
    const float* cow  = (const float*)d_in[23];
    const float* cob  = (const float*)d_in[24];
    float* out = (float*)d_out;

    float* buf = nullptr;
    cudaGetSymbolAddress((void**)&buf, g_buf);
    float* ab   = buf + OFF_AB;
    float* sa   = buf + OFF_SA;
    float* sb   = buf + OFF_SB;
    float* qp0  = buf + OFF_QP0;
    float* cf   = buf + OFF_CF;
    float* bsum = buf + OFF_BSUM;
    float* b2   = buf + OFF_B2;
    float* Mf   = buf + OFF_MF;
    float* wot  = buf + OFF_WOT;
    float* W2   = buf + OFF_W2;
    float4* pk  = (float4*)(buf + OFF_PK);
    float* hid  = buf + OFF_HID;
    float* ve   = buf + OFF_VE;
    float* g1   = buf + OFF_G1;
    float* kp   = buf + OFF_KP;
    float* vp   = buf + OFF_VP;
    float* O    = buf + OFF_O;
    float* xgv  = buf + OFF_XGV;
    float* xgg  = buf + OFF_XGG;
    float* H    = buf + OFF_H;
    float* H1   = buf + OFF_H1;
    float* H2   = buf + OFF_H2;
    float* prob = buf + OFF_PROB;

    cudaFuncSetAttribute(k_attn, cudaFuncAttributeMaxDynamicSharedMemorySize, ATTN_SHM_BYTES);

    // --- prep ---
    k_ab<<<1, 32>>>(betas, ab);
    k_sab<<<1, 256>>>(dt, ab, sa, sb);
    k_prep<<<6, 256>>>(wih, bih, bhh, ipw, ipb, opb, bsum, b2, cf, qp0);
    k_two<<<256, 256>>>(opw, wot);
    gemm_nt<<<dim3(4, 4),  256>>>(ipw, wot, nullptr, Mf, 256, 256, 256, 0);   // Mf = Wq@Wo
    gemm_nt<<<dim3(4, 16), 256>>>(wih, wot, nullptr, W2, 1024, 256, 256, 0);  // W2 = w_ih@Wo
    k_pack<<<256, 256>>>(whh, pk);

    // --- ve / gen1 ---
    k_hid<<<3200, 256>>>(st, tlw, tlb, hid);
    gemm_nt<<<dim3(4, 200), 256>>>(hid, tuw, tub, ve, 12800, 256, 64, 0);     // tenc -> ve
    k_ve<<<12800, 256>>>(seqs, emb, nn, pn, sa, sb, ve, g1);

    // --- K/V projections of gen1 ---
    gemm_nt<<<dim3(4, 200), 256>>>(g1, ipw + 256 * 256, ipb + 256, kp, 12800, 256, 256, 0);
    gemm_nt<<<dim3(4, 200), 256>>>(g1, ipw + 512 * 256, ipb + 512, vp, 12800, 256, 256, 0);

    // --- LSTM gate pre-activations for the ve branch ---
    gemm_nt<<<dim3(16, 200), 256>>>(ve, wih, bsum, xgv, 12800, 1024, 256, 0);

    // --- 50 serial attention steps ---
    for (int s = 0; s < VV; s++)
        k_attn<<<dim3(8, 16), 256, ATTN_SHM_BYTES>>>(s, kp, vp, O, Mf, cf, qp0);

    // --- LSTM gate pre-activations for the gen branch (Wo folded into W2) ---
    gemm_nt<<<dim3(16, 200), 256>>>(O, W2, b2, xgg, 12800, 1024, 256, 0);

    // --- LSTMs: 50 v-slices x 2 chains ---
    k_lstm<<<50, 256>>>(xgv, xgg, pk, H);

    // --- classifier ---
    gemm_nt<<<dim3(16, 2), 256>>>(H,  c1w, c1b, H1, 100, 1024, 256, 1);
    gemm_nt<<<dim3(16, 2), 256>>>(H1, c2w, c2b, H2, 100, 1024, 1024, 1);
    k_logits<<<1, 128>>>(H2, cow, cob, prob);

    // --- outputs ---
    k_out<<<204, 256>>>(prob, out);
    cudaMemcpyAsync(out + 52224,           nn, (size_t)BB * VV * DD * sizeof(float),
                    cudaMemcpyDeviceToDevice);
    cudaMemcpyAsync(out + 52224 + 3276800, pn, (size_t)BB * VV * DD * sizeof(float),
                    cudaMemcpyDeviceToDevice);
}

// round 15
// speedup vs baseline: 1.5494x; 1.5494x over previous
#include <cuda_runtime.h>
#include <cstddef>
#include <cstdint>
#include <math.h>

#define BB   256
#define VV   50
#define CC   40
#define DD   256
#define HH   256
#define TT   1000

// ---------------- scratch buffer (float offsets) ----------------
constexpr size_t OFF_AB   = 0;            // 1000
constexpr size_t OFF_SA   = 1024;         // 256
constexpr size_t OFF_SB   = 1280;         // 256
constexpr size_t OFF_QP0  = 1536;         // 256
constexpr size_t OFF_CF   = 1792;         // 256
constexpr size_t OFF_BSUM = 2048;         // 1024
constexpr size_t OFF_B2   = 3072;         // 1024
constexpr size_t OFF_MF   = 4096;         // 256*256
constexpr size_t OFF_WOT  = 69632;        // 256*256
constexpr size_t OFF_W2   = 135168;       // 1024*256
constexpr size_t OFF_PK   = 397312;       // 256*256*4 floats (float4-packed w_hh)
constexpr size_t OFF_HID  = 659456;       // 12800*64
constexpr size_t OFF_VE   = 1478656;      // 12800*256
constexpr size_t OFF_G1   = 4755456;      // 12800*256
constexpr size_t OFF_KP   = 8032256;      // 12800*256
constexpr size_t OFF_VP   = 11309056;     // 12800*256
constexpr size_t OFF_O    = 14585856;     // 12800*256 (pre-out-proj attn outputs)
constexpr size_t OFF_XGV  = 17862656;     // 12800*1024
constexpr size_t OFF_XGG  = 30969856;     // 12800*1024
constexpr size_t OFF_H    = 44077056;     // 100*256 (rows 0..49 hv, 50..99 hg)
constexpr size_t OFF_H1   = 44102656;     // 100*1024
constexpr size_t OFF_H2   = 44205056;     // 100*1024
constexpr size_t OFF_PROB = 44307456;     // 100*2
constexpr size_t BUF_SIZE = 44307656;

__device__ float g_buf[BUF_SIZE];

__device__ __forceinline__ float sigf(float x) { return 1.0f / (1.0f + expf(-x)); }

// ---------------- tiny prep kernels ----------------
__global__ void k_ab(const float* __restrict__ betas, float* __restrict__ ab) {
    if (threadIdx.x == 0) {
        float p = 1.0f;
        for (int i = 0; i < TT; i++) { p *= (1.0f - betas[i]); ab[i] = p; }
    }
}

__global__ void k_sab(const int* __restrict__ dt, const float* __restrict__ ab,
                      float* __restrict__ sa, float* __restrict__ sb) {
    int b = threadIdx.x;
    float a = ab[dt[b]];
    sa[b] = sqrtf(a);
    sb[b] = sqrtf(fmaxf(1.0f - a, 0.0f));
}

__global__ void k_prep(const float* __restrict__ wih, const float* __restrict__ bih,
                       const float* __restrict__ bhh, const float* __restrict__ ipw,
                       const float* __restrict__ ipb, const float* __restrict__ opb,
                       float* __restrict__ bsum, float* __restrict__ b2,
                       float* __restrict__ cf, float* __restrict__ qp0) {
    int j = blockIdx.x * 256 + threadIdx.x;
    if (j < 1024) {
        float acc = 0.0f;
        const float* wr = wih + (size_t)j * 256;
        for (int d = 0; d < 256; d++) acc += wr[d] * opb[d];
        bsum[j] = bih[j] + bhh[j];
        b2[j]   = acc + bih[j] + bhh[j];
    } else if (j < 1280) {
        int jj = j - 1024;
        float acc = 0.0f;
        const float* wr = ipw + (size_t)jj * 256;   // Wq row
        for (int d = 0; d < 256; d++) acc += wr[d] * opb[d];
        cf[jj] = acc + ipb[jj];
    } else if (j < 1536) {
        int jj = j - 1280;
        float acc = 0.0f;
        const float* wr = ipw + (size_t)jj * 256;
        for (int d = 0; d < 256; d++) acc += wr[d];
        qp0[jj] = 10000.0f * acc + ipb[jj];
    }
}

__global__ void k_two(const float* __restrict__ wo, float* __restrict__ wot) {
    int e = blockIdx.x, d = threadIdx.x;
    wot[e * 256 + d] = wo[d * 256 + e];     // wot[e,d] = Wo[d,e]
}

__global__ void k_pack(const float* __restrict__ whh, float4* __restrict__ pk) {
    int d = blockIdx.x, j = threadIdx.x;
    pk[d * 256 + j] = make_float4(whh[(0   + j) * 256 + d],
                                  whh[(256 + j) * 256 + d],
                                  whh[(512 + j) * 256 + d],
                                  whh[(768 + j) * 256 + d]);
}

// hid[r*64+k], r = v*256+b
__global__ void k_hid(const float* __restrict__ st, const float* __restrict__ tlw,
                      const float* __restrict__ tlb, float* __restrict__ hid) {
    int gid = blockIdx.x * 256 + threadIdx.x;
    int k = gid & 63;
    int r = gid >> 6;
    int v = r >> 8, b = r & 255;
    float tt = st[b * VV + v] * (1.0f / 180.0f);
    float x = tt * tlw[k] + tlb[k];
    hid[gid] = 1.0f - tanhf(x * x);
}

// ve (tenc already in place) += embedding gather; then gen1
__global__ void k_ve(const int* __restrict__ seqs, const float* __restrict__ emb,
                     const float* __restrict__ nn, const float* __restrict__ pn,
                     const float* __restrict__ sa, const float* __restrict__ sb,
                     float* __restrict__ ve, float* __restrict__ g1) {
    __shared__ int sidx[CC];
    int r = blockIdx.x;
    int d = threadIdx.x;
    int v = r >> 8, b = r & 255;
    if (d < CC) sidx[d] = seqs[(b * VV + v) * CC + d];
    __syncthreads();
    float acc = ve[(size_t)r * 256 + d];   // tenc
#pragma unroll 8
    for (int c = 0; c < CC; c++)
        acc += fmaxf(emb[(size_t)sidx[c] * 256 + d], 0.0f);
    ve[(size_t)r * 256 + d] = acc;
    size_t ni = ((size_t)b * VV + v) * 256 + d;
    g1[(size_t)r * 256 + d] = acc * (1.0f + sa[b]) + nn[ni] * sb[b] - pn[ni];
}

// ---------------- generic tiled SGEMM: C[M,N] = A[M,K] @ B[N,K]^T (+bias)(+relu) --------
__global__ void gemm_nt(const float* __restrict__ A, const float* __restrict__ B,
                        const float* __restrict__ bias, float* __restrict__ C,
                        int M, int N, int K, int relu) {
    __shared__ float As[16 * 68];
    __shared__ float Bs[16 * 68];
    int tid = threadIdx.x;
    int tx = tid & 15, ty = tid >> 4;
    int n0 = blockIdx.x * 64, m0 = blockIdx.y * 64;
    int lr = tid >> 2;            // 0..63
    int lk = (tid & 3) * 4;       // 0,4,8,12
    float acc[4][4] = {};
    for (int k0 = 0; k0 < K; k0 += 16) {
        __syncthreads();
        int ar = m0 + lr;
        float4 av = (ar < M) ? *reinterpret_cast<const float4*>(A + (size_t)ar * K + k0 + lk)
                             : make_float4(0.f, 0.f, 0.f, 0.f);
        float4 bv = *reinterpret_cast<const float4*>(B + (size_t)(n0 + lr) * K + k0 + lk);
        As[(lk + 0) * 68 + lr] = av.x;
        As[(lk + 1) * 68 + lr] = av.y;
        As[(lk + 2) * 68 + lr] = av.z;
        As[(lk + 3) * 68 + lr] = av.w;
        Bs[(lk + 0) * 68 + lr] = bv.x;
        Bs[(lk + 1) * 68 + lr] = bv.y;
        Bs[(lk + 2) * 68 + lr] = bv.z;
        Bs[(lk + 3) * 68 + lr] = bv.w;
        __syncthreads();
#pragma unroll
        for (int kk = 0; kk < 16; kk++) {
            float4 a = *reinterpret_cast<const float4*>(As + kk * 68 + ty * 4);
            float4 b = *reinterpret_cast<const float4*>(Bs + kk * 68 + tx * 4);
            acc[0][0] += a.x * b.x; acc[0][1] += a.x * b.y; acc[0][2] += a.x * b.z; acc[0][3] += a.x * b.w;
            acc[1][0] += a.y * b.x; acc[1][1] += a.y * b.y; acc[1][2] += a.y * b.z; acc[1][3] += a.y * b.w;
            acc[2][0] += a.z * b.x; acc[2][1] += a.z * b.y; acc[2][2] += a.z * b.z; acc[2][3] += a.z * b.w;
            acc[3][0] += a.w * b.x; acc[3][1] += a.w * b.y; acc[3][2] += a.w * b.z; acc[3][3] += a.w * b.w;
        }
    }
#pragma unroll
    for (int i = 0; i < 4; i++) {
        int row = m0 + ty * 4 + i;
        if (row < M) {
#pragma unroll
            for (int j = 0; j < 4; j++) {
                int col = n0 + tx * 4 + j;
                float vout = acc[i][j] + (bias ? bias[col] : 0.0f);
                if (relu) vout = fmaxf(vout, 0.0f);
                C[(size_t)row * N + col] = vout;
            }
        }
    }
}

// ---------------- fused attention step ----------------
// qp_i = O_{i-1} @ M^T + c  (M = Wq@Wo, c = Wq@bo + bq); step0: all q rows = qp0
// scores -> softmax -> O_i = P @ Vp   (O is PRE-out-projection)
#define ATTN_SHM_FLOATS (256*33*2 + 16*256 + 32*257 + 16*32 + 16*256)
#define ATTN_SHM_BYTES  (ATTN_SHM_FLOATS * 4)

__global__ void k_attn(int step, const float* __restrict__ kp, const float* __restrict__ vp,
                       float* __restrict__ O, const float* __restrict__ Mf,
                       const float* __restrict__ cf, const float* __restrict__ qp0) {
    extern __shared__ float sm[];
    float* kps = sm;                    // 256 keys x 32 hd, stride 33
    float* vps = kps + 256 * 33;
    float* oq  = vps + 256 * 33;        // 16 x 256 prev-O rows
    float* Ms  = oq + 16 * 256;         // 32 x 257 M rows for this head
    float* qps = Ms + 32 * 257;         // 16 x 32
    float* ss  = qps + 16 * 32;         // 16 x 256 scores

    int tid = threadIdx.x;
    int head = blockIdx.x, qt = blockIdx.y;
    int q0 = qt * 16;
    const float* kpv = kp + (size_t)step * (BB * DD);
    const float* vpv = vp + (size_t)step * (BB * DD);

    for (int idx = tid; idx < 256 * 32; idx += 256) {
        int k = idx >> 5, hd = idx & 31;
        kps[k * 33 + hd] = kpv[k * 256 + head * 32 + hd];
        vps[k * 33 + hd] = vpv[k * 256 + head * 32 + hd];
    }
    if (step > 0) {
        const float* Op = O + (size_t)(step - 1) * (BB * DD);
        for (int idx = tid; idx < 16 * 256; idx += 256)
            oq[idx] = Op[(q0 + (idx >> 8)) * 256 + (idx & 255)];
        for (int idx = tid; idx < 32 * 256; idx += 256) {
            int j = idx >> 8, e = idx & 255;
            Ms[j * 257 + e] = Mf[(head * 32 + j) * 256 + e];
        }
    }
    __syncthreads();

    int jl = tid & 31, qi = tid >> 5;
    if (step == 0) {
        float vq = qp0[head * 32 + jl];
        qps[qi * 32 + jl] = vq;
        qps[(qi + 8) * 32 + jl] = vq;
    } else {
        for (int qq = qi; qq < 16; qq += 8) {
            float acc = cf[head * 32 + jl];
            const float* orow = oq + qq * 256;
            const float* mrow = Ms + jl * 257;
#pragma unroll 8
            for (int e = 0; e < 256; e++) acc += orow[e] * mrow[e];
            qps[qq * 32 + jl] = acc;
        }
    }
    __syncthreads();

    {   // scores: one key per thread
        int k = tid;
        const float* krow = kps + k * 33;
#pragma unroll
        for (int q = 0; q < 16; q++) {
            const float* qrow = qps + q * 32;
            float acc = 0.0f;
#pragma unroll
            for (int hd = 0; hd < 32; hd++) acc += qrow[hd] * krow[hd];
            ss[q * 256 + k] = acc * 0.17677669529663687f;  // 1/sqrt(32)
        }
    }
    __syncthreads();

    {   // softmax over k; warp w handles q rows w and w+8
        int lane = tid & 31, w = tid >> 5;
        for (int q = w; q < 16; q += 8) {
            float* row = ss + q * 256;
            float vv[8];
            float mx = -1e30f;
#pragma unroll
            for (int m = 0; m < 8; m++) { vv[m] = row[lane + 32 * m]; mx = fmaxf(mx, vv[m]); }
#pragma unroll
            for (int o = 16; o; o >>= 1) mx = fmaxf(mx, __shfl_xor_sync(0xFFFFFFFFu, mx, o));
            float sum = 0.0f;
#pragma unroll
            for (int m = 0; m < 8; m++) { vv[m] = expf(vv[m] - mx); sum += vv[m]; }
#pragma unroll
            for (int o = 16; o; o >>= 1) sum += __shfl_xor_sync(0xFFFFFFFFu, sum, o);
            float inv = 1.0f / sum;
#pragma unroll
            for (int m = 0; m < 8; m++) row[lane + 32 * m] = vv[m] * inv;
        }
    }
    __syncthreads();

    {   // O = P @ Vp
        int hd = tid & 31, qi2 = tid >> 5;
        float* Oo = O + (size_t)step * (BB * DD);
        for (int qq = qi2; qq < 16; qq += 8) {
            const float* prow = ss + qq * 256;
            float acc = 0.0f;
#pragma unroll 8
            for (int k = 0; k < 256; k++) acc += prow[k] * vps[k * 33 + hd];
            Oo[(q0 + qq) * 256 + head * 32 + hd] = acc;
        }
    }
}

// ---------------- LSTM v2: 50 blocks x 512 threads ----------------
// 2 chains per block (ve + gen for one v). Hidden-dim reduction split across
// two 256-thread halves (d in [0,128) / [128,256)), partials combined in smem.
// Weight loads batched 16-deep so the LDG stream saturates L1/L2 throughput
// instead of being L2-latency-bound.
__global__ void __launch_bounds__(512, 1)
k_lstm(const float* __restrict__ xgv, const float* __restrict__ xgg,
       const float4* __restrict__ pk, float* __restrict__ hout) {
    __shared__ float2 hs[256];
    __shared__ float red[256][9];   // padded: stride 9 -> conflict-free
    int v = blockIdx.x, tid = threadIdx.x;
    int col = tid & 255, half = tid >> 8;
    if (tid < 256) hs[tid] = make_float2(0.0f, 0.0f);
    float c0 = 0.0f, c1 = 0.0f;
    const float* x0 = xgv + (size_t)v * 256 * 1024;
    const float* x1 = xgg + (size_t)v * 256 * 1024;
    const float4* pkh = pk + (size_t)half * 128 * 256;
    __syncthreads();
    for (int t = 0; t < 256; t++) {
        float i0, f0, g0, o0, i1, f1, g1, o1;
        if (half == 0) {
            const float* a0 = x0 + (size_t)t * 1024;
            const float* a1 = x1 + (size_t)t * 1024;
            i0 = a0[col]; f0 = a0[col + 256]; g0 = a0[col + 512]; o0 = a0[col + 768];
            i1 = a1[col]; f1 = a1[col + 256]; g1 = a1[col + 512]; o1 = a1[col + 768];
        } else {
            i0 = f0 = g0 = o0 = i1 = f1 = g1 = o1 = 0.0f;
        }
        const float2* hb = hs + half * 128;
        for (int d0 = 0; d0 < 128; d0 += 16) {
            float4 w[16];
#pragma unroll
            for (int i = 0; i < 16; i++) w[i] = pkh[(size_t)(d0 + i) * 256 + col];
#pragma unroll
            for (int i = 0; i < 16; i++) {
                float2 h = hb[d0 + i];
                i0 += w[i].x * h.x; f0 += w[i].y * h.x; g0 += w[i].z * h.x; o0 += w[i].w * h.x;
                i1 += w[i].x * h.y; f1 += w[i].y * h.y; g1 += w[i].z * h.y; o1 += w[i].w * h.y;
            }
        }
        if (half == 1) {
            red[col][0] = i0; red[col][1] = f0; red[col][2] = g0; red[col][3] = o0;
            red[col][4] = i1; red[col][5] = f1; red[col][6] = g1; red[col][7] = o1;
        }
        __syncthreads();
        if (half == 0) {
            i0 += red[col][0]; f0 += red[col][1]; g0 += red[col][2]; o0 += red[col][3];
            i1 += red[col][4]; f1 += red[col][5]; g1 += red[col][6]; o1 += red[col][7];
            c0 = sigf(f0) * c0 + sigf(i0) * tanhf(g0);
            float h0 = sigf(o0) * tanhf(c0);
            c1 = sigf(f1) * c1 + sigf(i1) * tanhf(g1);
            float h1 = sigf(o1) * tanhf(c1);
            hs[col] = make_float2(h0, h1);
            if (t == 255) {
                hout[v * 256 + col]        = h0;
                hout[(VV + v) * 256 + col] = h1;
            }
        }
        __syncthreads();
    }
}

// ---------------- logits + softmax over 2 classes ----------------
__global__ void k_logits(const float* __restrict__ h2, const float* __restrict__ cow,
                         const float* __restrict__ cob, float* __restrict__ probs) {
    int t = blockIdx.x * blockDim.x + threadIdx.x;
    if (t >= 100) return;
    const float* hr = h2 + (size_t)t * 1024;
    float l0 = cob[0], l1 = cob[1];
    for (int d = 0; d < 1024; d++) { l0 += hr[d] * cow[d]; l1 += hr[d] * cow[1024 + d]; }
    float m = fmaxf(l0, l1);
    float e0 = expf(l0 - m), e1 = expf(l1 - m);
    float s = e0 + e1;
    probs[t * 2 + 0] = e0 / s;
    probs[t * 2 + 1] = e1 / s;
}

// ---------------- output assembly: first 52224 floats ----------------
__global__ void k_out(const float* __restrict__ probs, float* __restrict__ out) {
    int i = blockIdx.x * 256 + threadIdx.x;
    if (i >= 52224) return;
    float val;
    if (i < 25600) {                       // res [B,V,2]
        int v = (i >> 1) % 50;
        val = probs[v * 2 + (i & 1)];
    } else if (i < 51200) {                // resg [B,V,2]
        int j = i - 25600;
        int v = (j >> 1) % 50;
        val = probs[(50 + v) * 2 + (j & 1)];
    } else if (i < 51712) {                // res[:, -1]
        val = probs[98 + (i & 1)];
    } else {                               // resg[:, -1]
        val = probs[198 + (i & 1)];
    }
    out[i] = val;
}

// ---------------- host launcher ----------------
extern "C" void kernel_launch(void* const* d_in, const int* in_sizes, int n_in,
                              void* d_out, int out_size) {
    (void)in_sizes; (void)n_in; (void)out_size;
    const int*   seqs = (const int*)  d_in[0];
    const float* st   = (const float*)d_in[1];
    const int*   dt   = (const int*)  d_in[2];
    const float* nn   = (const float*)d_in[3];
    const float* pn   = (const float*)d_in[4];
    const float* emb  = (const float*)d_in[5];
    const float* betas= (const float*)d_in[6];
    const float* tlw  = (const float*)d_in[7];
    const float* tlb  = (const float*)d_in[8];
    const float* tuw  = (const float*)d_in[9];
    const float* tub  = (const float*)d_in[10];
    const float* ipw  = (const float*)d_in[11];
    const float* ipb  = (const float*)d_in[12];
    const float* opw  = (const float*)d_in[13];
    const float* opb  = (const float*)d_in[14];
    const float* wih  = (const float*)d_in[15];
    const float* whh  = (const float*)d_in[16];
    const float* bih  = (const float*)d_in[17];
    const float* bhh  = (const float*)d_in[18];
    const float* c1w  = (const float*)d_in[19];
    const float* c1b  = (const float*)d_in[20];
    const float* c2w  = (const float*)d_in[21];
    const float* c2b  = (const float*)d_in[22];
    const float* cow  = (const float*)d_in[23];
    const float* cob  = (const float*)d_in[24];
    float* out = (float*)d_out;

    float* buf = nullptr;
    cudaGetSymbolAddress((void**)&buf, g_buf);
    float* ab   = buf + OFF_AB;
    float* sa   = buf + OFF_SA;
    float* sb   = buf + OFF_SB;
    float* qp0  = buf + OFF_QP0;
    float* cf   = buf + OFF_CF;
    float* bsum = buf + OFF_BSUM;
    float* b2   = buf + OFF_B2;
    float* Mf   = buf + OFF_MF;
    float* wot  = buf + OFF_WOT;
    float* W2   = buf + OFF_W2;
    float4* pk  = (float4*)(buf + OFF_PK);
    float* hid  = buf + OFF_HID;
    float* ve   = buf + OFF_VE;
    float* g1   = buf + OFF_G1;
    float* kp   = buf + OFF_KP;
    float* vp   = buf + OFF_VP;
    float* O    = buf + OFF_O;
    float* xgv  = buf + OFF_XGV;
    float* xgg  = buf + OFF_XGG;
    float* H    = buf + OFF_H;
    float* H1   = buf + OFF_H1;
    float* H2   = buf + OFF_H2;
    float* prob = buf + OFF_PROB;

    cudaFuncSetAttribute(k_attn, cudaFuncAttributeMaxDynamicSharedMemorySize, ATTN_SHM_BYTES);

    // --- prep ---
    k_ab<<<1, 32>>>(betas, ab);
    k_sab<<<1, 256>>>(dt, ab, sa, sb);
    k_prep<<<6, 256>>>(wih, bih, bhh, ipw, ipb, opb, bsum, b2, cf, qp0);
    k_two<<<256, 256>>>(opw, wot);
    gemm_nt<<<dim3(4, 4),  256>>>(ipw, wot, nullptr, Mf, 256, 256, 256, 0);   // Mf = Wq@Wo
    gemm_nt<<<dim3(4, 16), 256>>>(wih, wot, nullptr, W2, 1024, 256, 256, 0);  // W2 = w_ih@Wo
    k_pack<<<256, 256>>>(whh, pk);

    // --- ve / gen1 ---
    k_hid<<<3200, 256>>>(st, tlw, tlb, hid);
    gemm_nt<<<dim3(4, 200), 256>>>(hid, tuw, tub, ve, 12800, 256, 64, 0);     // tenc -> ve
    k_ve<<<12800, 256>>>(seqs, emb, nn, pn, sa, sb, ve, g1);

    // --- K/V projections of gen1 ---
    gemm_nt<<<dim3(4, 200), 256>>>(g1, ipw + 256 * 256, ipb + 256, kp, 12800, 256, 256, 0);
    gemm_nt<<<dim3(4, 200), 256>>>(g1, ipw + 512 * 256, ipb + 512, vp, 12800, 256, 256, 0);

    // --- LSTM gate pre-activations for the ve branch ---
    gemm_nt<<<dim3(16, 200), 256>>>(ve, wih, bsum, xgv, 12800, 1024, 256, 0);

    // --- 50 serial attention steps ---
    for (int s = 0; s < VV; s++)
        k_attn<<<dim3(8, 16), 256, ATTN_SHM_BYTES>>>(s, kp, vp, O, Mf, cf, qp0);

    // --- LSTM gate pre-activations for the gen branch (Wo folded into W2) ---
    gemm_nt<<<dim3(16, 200), 256>>>(O, W2, b2, xgg, 12800, 1024, 256, 0);

    // --- LSTMs: 50 v-slices x 2 chains, split-K over hidden dim ---
    k_lstm<<<50, 512>>>(xgv, xgg, pk, H);

    // --- classifier ---
    gemm_nt<<<dim3(16, 2), 256>>>(H,  c1w, c1b, H1, 100, 1024, 256, 1);
    gemm_nt<<<dim3(16, 2), 256>>>(H1, c2w, c2b, H2, 100, 1024, 1024, 1);
    k_logits<<<1, 128>>>(H2, cow, cob, prob);

    // --- outputs ---
    k_out<<<204, 256>>>(prob, out);
    cudaMemcpyAsync(out + 52224,           nn, (size_t)BB * VV * DD * sizeof(float),
                    cudaMemcpyDeviceToDevice);
    cudaMemcpyAsync(out + 52224 + 3276800, pn, (size_t)BB * VV * DD * sizeof(float),
                    cudaMemcpyDeviceToDevice);
}

// round 16
// speedup vs baseline: 1.9040x; 1.2288x over previous
#include <cuda_runtime.h>
#include <cstddef>
#include <cstdint>
#include <math.h>

#define BB   256
#define VV   50
#define CC   40
#define DD   256
#define HH   256
#define TT   1000

// ---------------- scratch buffer (float offsets) ----------------
constexpr size_t OFF_AB   = 0;            // 1000
constexpr size_t OFF_SA   = 1024;         // 256
constexpr size_t OFF_SB   = 1280;         // 256
constexpr size_t OFF_QP0  = 1536;         // 256
constexpr size_t OFF_CF   = 1792;         // 256
constexpr size_t OFF_BSUM = 2048;         // 1024
constexpr size_t OFF_B2   = 3072;         // 1024
constexpr size_t OFF_MF   = 4096;         // 256*256
constexpr size_t OFF_WOT  = 69632;        // 256*256
constexpr size_t OFF_W2   = 135168;       // 1024*256
constexpr size_t OFF_PK   = 397312;       // 256*256*4 floats (float4-packed w_hh)
constexpr size_t OFF_HID  = 659456;       // 12800*64
constexpr size_t OFF_VE   = 1478656;      // 12800*256
constexpr size_t OFF_G1   = 4755456;      // 12800*256
constexpr size_t OFF_KP   = 8032256;      // 12800*256
constexpr size_t OFF_VP   = 11309056;     // 12800*256
constexpr size_t OFF_O    = 14585856;     // 12800*256 (pre-out-proj attn outputs)
constexpr size_t OFF_XGV  = 17862656;     // 12800*1024
constexpr size_t OFF_XGG  = 30969856;     // 12800*1024
constexpr size_t OFF_H    = 44077056;     // 100*256 (rows 0..49 hv, 50..99 hg)
constexpr size_t OFF_H1   = 44102656;     // 100*1024
constexpr size_t OFF_H2   = 44205056;     // 100*1024
constexpr size_t OFF_PROB = 44307456;     // 100*2
constexpr size_t BUF_SIZE = 44307656;

__device__ float g_buf[BUF_SIZE];

__device__ __forceinline__ float sigf(float x) { return 1.0f / (1.0f + expf(-x)); }

// ---------------- tiny prep kernels ----------------
__global__ void k_ab(const float* __restrict__ betas, float* __restrict__ ab) {
    if (threadIdx.x == 0) {
        float p = 1.0f;
        for (int i = 0; i < TT; i++) { p *= (1.0f - betas[i]); ab[i] = p; }
    }
}

__global__ void k_sab(const int* __restrict__ dt, const float* __restrict__ ab,
                      float* __restrict__ sa, float* __restrict__ sb) {
    int b = threadIdx.x;
    float a = ab[dt[b]];
    sa[b] = sqrtf(a);
    sb[b] = sqrtf(fmaxf(1.0f - a, 0.0f));
}

__global__ void k_prep(const float* __restrict__ wih, const float* __restrict__ bih,
                       const float* __restrict__ bhh, const float* __restrict__ ipw,
                       const float* __restrict__ ipb, const float* __restrict__ opb,
                       float* __restrict__ bsum, float* __restrict__ b2,
                       float* __restrict__ cf, float* __restrict__ qp0) {
    int j = blockIdx.x * 256 + threadIdx.x;
    if (j < 1024) {
        float acc = 0.0f;
        const float* wr = wih + (size_t)j * 256;
        for (int d = 0; d < 256; d++) acc += wr[d] * opb[d];
        bsum[j] = bih[j] + bhh[j];
        b2[j]   = acc + bih[j] + bhh[j];
    } else if (j < 1280) {
        int jj = j - 1024;
        float acc = 0.0f;
        const float* wr = ipw + (size_t)jj * 256;   // Wq row
        for (int d = 0; d < 256; d++) acc += wr[d] * opb[d];
        cf[jj] = acc + ipb[jj];
    } else if (j < 1536) {
        int jj = j - 1280;
        float acc = 0.0f;
        const float* wr = ipw + (size_t)jj * 256;
        for (int d = 0; d < 256; d++) acc += wr[d];
        qp0[jj] = 10000.0f * acc + ipb[jj];
    }
}

__global__ void k_two(const float* __restrict__ wo, float* __restrict__ wot) {
    int e = blockIdx.x, d = threadIdx.x;
    wot[e * 256 + d] = wo[d * 256 + e];     // wot[e,d] = Wo[d,e]
}

__global__ void k_pack(const float* __restrict__ whh, float4* __restrict__ pk) {
    int d = blockIdx.x, j = threadIdx.x;
    pk[d * 256 + j] = make_float4(whh[(0   + j) * 256 + d],
                                  whh[(256 + j) * 256 + d],
                                  whh[(512 + j) * 256 + d],
                                  whh[(768 + j) * 256 + d]);
}

// hid[r*64+k], r = v*256+b
__global__ void k_hid(const float* __restrict__ st, const float* __restrict__ tlw,
                      const float* __restrict__ tlb, float* __restrict__ hid) {
    int gid = blockIdx.x * 256 + threadIdx.x;
    int k = gid & 63;
    int r = gid >> 6;
    int v = r >> 8, b = r & 255;
    float tt = st[b * VV + v] * (1.0f / 180.0f);
    float x = tt * tlw[k] + tlb[k];
    hid[gid] = 1.0f - tanhf(x * x);
}

// ve (tenc already in place) += embedding gather; then gen1
__global__ void k_ve(const int* __restrict__ seqs, const float* __restrict__ emb,
                     const float* __restrict__ nn, const float* __restrict__ pn,
                     const float* __restrict__ sa, const float* __restrict__ sb,
                     float* __restrict__ ve, float* __restrict__ g1) {
    __shared__ int sidx[CC];
    int r = blockIdx.x;
    int d = threadIdx.x;
    int v = r >> 8, b = r & 255;
    if (d < CC) sidx[d] = seqs[(b * VV + v) * CC + d];
    __syncthreads();
    float acc = ve[(size_t)r * 256 + d];   // tenc
#pragma unroll 8
    for (int c = 0; c < CC; c++)
        acc += fmaxf(emb[(size_t)sidx[c] * 256 + d], 0.0f);
    ve[(size_t)r * 256 + d] = acc;
    size_t ni = ((size_t)b * VV + v) * 256 + d;
    g1[(size_t)r * 256 + d] = acc * (1.0f + sa[b]) + nn[ni] * sb[b] - pn[ni];
}

// ---------------- generic tiled SGEMM: C[M,N] = A[M,K] @ B[N,K]^T (+bias)(+relu) --------
__global__ void gemm_nt(const float* __restrict__ A, const float* __restrict__ B,
                        const float* __restrict__ bias, float* __restrict__ C,
                        int M, int N, int K, int relu) {
    __shared__ float As[16 * 68];
    __shared__ float Bs[16 * 68];
    int tid = threadIdx.x;
    int tx = tid & 15, ty = tid >> 4;
    int n0 = blockIdx.x * 64, m0 = blockIdx.y * 64;
    int lr = tid >> 2;            // 0..63
    int lk = (tid & 3) * 4;       // 0,4,8,12
    float acc[4][4] = {};
    for (int k0 = 0; k0 < K; k0 += 16) {
        __syncthreads();
        int ar = m0 + lr;
        float4 av = (ar < M) ? *reinterpret_cast<const float4*>(A + (size_t)ar * K + k0 + lk)
                             : make_float4(0.f, 0.f, 0.f, 0.f);
        float4 bv = *reinterpret_cast<const float4*>(B + (size_t)(n0 + lr) * K + k0 + lk);
        As[(lk + 0) * 68 + lr] = av.x;
        As[(lk + 1) * 68 + lr] = av.y;
        As[(lk + 2) * 68 + lr] = av.z;
        As[(lk + 3) * 68 + lr] = av.w;
        Bs[(lk + 0) * 68 + lr] = bv.x;
        Bs[(lk + 1) * 68 + lr] = bv.y;
        Bs[(lk + 2) * 68 + lr] = bv.z;
        Bs[(lk + 3) * 68 + lr] = bv.w;
        __syncthreads();
#pragma unroll
        for (int kk = 0; kk < 16; kk++) {
            float4 a = *reinterpret_cast<const float4*>(As + kk * 68 + ty * 4);
            float4 b = *reinterpret_cast<const float4*>(Bs + kk * 68 + tx * 4);
            acc[0][0] += a.x * b.x; acc[0][1] += a.x * b.y; acc[0][2] += a.x * b.z; acc[0][3] += a.x * b.w;
            acc[1][0] += a.y * b.x; acc[1][1] += a.y * b.y; acc[1][2] += a.y * b.z; acc[1][3] += a.y * b.w;
            acc[2][0] += a.z * b.x; acc[2][1] += a.z * b.y; acc[2][2] += a.z * b.z; acc[2][3] += a.z * b.w;
            acc[3][0] += a.w * b.x; acc[3][1] += a.w * b.y; acc[3][2] += a.w * b.z; acc[3][3] += a.w * b.w;
        }
    }
#pragma unroll
    for (int i = 0; i < 4; i++) {
        int row = m0 + ty * 4 + i;
        if (row < M) {
#pragma unroll
            for (int j = 0; j < 4; j++) {
                int col = n0 + tx * 4 + j;
                float vout = acc[i][j] + (bias ? bias[col] : 0.0f);
                if (relu) vout = fmaxf(vout, 0.0f);
                C[(size_t)row * N + col] = vout;
            }
        }
    }
}

// ---------------- fused attention step ----------------
#define ATTN_SHM_FLOATS (256*33*2 + 16*256 + 32*257 + 16*32 + 16*256)
#define ATTN_SHM_BYTES  (ATTN_SHM_FLOATS * 4)

__global__ void k_attn(int step, const float* __restrict__ kp, const float* __restrict__ vp,
                       float* __restrict__ O, const float* __restrict__ Mf,
                       const float* __restrict__ cf, const float* __restrict__ qp0) {
    extern __shared__ float sm[];
    float* kps = sm;                    // 256 keys x 32 hd, stride 33
    float* vps = kps + 256 * 33;
    float* oq  = vps + 256 * 33;        // 16 x 256 prev-O rows
    float* Ms  = oq + 16 * 256;         // 32 x 257 M rows for this head
    float* qps = Ms + 32 * 257;         // 16 x 32
    float* ss  = qps + 16 * 32;         // 16 x 256 scores

    int tid = threadIdx.x;
    int head = blockIdx.x, qt = blockIdx.y;
    int q0 = qt * 16;
    const float* kpv = kp + (size_t)step * (BB * DD);
    const float* vpv = vp + (size_t)step * (BB * DD);

    for (int idx = tid; idx < 256 * 32; idx += 256) {
        int k = idx >> 5, hd = idx & 31;
        kps[k * 33 + hd] = kpv[k * 256 + head * 32 + hd];
        vps[k * 33 + hd] = vpv[k * 256 + head * 32 + hd];
    }
    if (step > 0) {
        const float* Op = O + (size_t)(step - 1) * (BB * DD);
        for (int idx = tid; idx < 16 * 256; idx += 256)
            oq[idx] = Op[(q0 + (idx >> 8)) * 256 + (idx & 255)];
        for (int idx = tid; idx < 32 * 256; idx += 256) {
            int j = idx >> 8, e = idx & 255;
            Ms[j * 257 + e] = Mf[(head * 32 + j) * 256 + e];
        }
    }
    __syncthreads();

    int jl = tid & 31, qi = tid >> 5;
    if (step == 0) {
        float vq = qp0[head * 32 + jl];
        qps[qi * 32 + jl] = vq;
        qps[(qi + 8) * 32 + jl] = vq;
    } else {
        for (int qq = qi; qq < 16; qq += 8) {
            float acc = cf[head * 32 + jl];
            const float* orow = oq + qq * 256;
            const float* mrow = Ms + jl * 257;
#pragma unroll 8
            for (int e = 0; e < 256; e++) acc += orow[e] * mrow[e];
            qps[qq * 32 + jl] = acc;
        }
    }
    __syncthreads();

    {   // scores: one key per thread
        int k = tid;
        const float* krow = kps + k * 33;
#pragma unroll
        for (int q = 0; q < 16; q++) {
            const float* qrow = qps + q * 32;
            float acc = 0.0f;
#pragma unroll
            for (int hd = 0; hd < 32; hd++) acc += qrow[hd] * krow[hd];
            ss[q * 256 + k] = acc * 0.17677669529663687f;  // 1/sqrt(32)
        }
    }
    __syncthreads();

    {   // softmax over k; warp w handles q rows w and w+8
        int lane = tid & 31, w = tid >> 5;
        for (int q = w; q < 16; q += 8) {
            float* row = ss + q * 256;
            float vv[8];
            float mx = -1e30f;
#pragma unroll
            for (int m = 0; m < 8; m++) { vv[m] = row[lane + 32 * m]; mx = fmaxf(mx, vv[m]); }
#pragma unroll
            for (int o = 16; o; o >>= 1) mx = fmaxf(mx, __shfl_xor_sync(0xFFFFFFFFu, mx, o));
            float sum = 0.0f;
#pragma unroll
            for (int m = 0; m < 8; m++) { vv[m] = expf(vv[m] - mx); sum += vv[m]; }
#pragma unroll
            for (int o = 16; o; o >>= 1) sum += __shfl_xor_sync(0xFFFFFFFFu, sum, o);
            float inv = 1.0f / sum;
#pragma unroll
            for (int m = 0; m < 8; m++) row[lane + 32 * m] = vv[m] * inv;
        }
    }
    __syncthreads();

    {   // O = P @ Vp
        int hd = tid & 31, qi2 = tid >> 5;
        float* Oo = O + (size_t)step * (BB * DD);
        for (int qq = qi2; qq < 16; qq += 8) {
            const float* prow = ss + qq * 256;
            float acc = 0.0f;
#pragma unroll 8
            for (int k = 0; k < 256; k++) acc += prow[k] * vps[k * 33 + hd];
            Oo[(q0 + qq) * 256 + head * 32 + hd] = acc;
        }
    }
}

// ---------------- LSTM v3: 50 clusters x 2 CTAs, gate-dim split via DSMEM ----------------
// Cluster CTA r handles gate columns j in [r*128, (r+1)*128) for both chains of one v.
// Per step: stream 512KB of weights, 4-way split-d partial reduce in smem, finisher
// threads apply nonlinearity and broadcast their 128 h values to both CTAs' double-
// buffered smem h via mapa + st.shared::cluster; ONE cluster barrier per step.
__global__ void __launch_bounds__(512, 1) __cluster_dims__(2, 1, 1)
k_lstm(const float* __restrict__ xgv, const float* __restrict__ xgg,
       const float4* __restrict__ pk, float* __restrict__ hout) {
    __shared__ float hbufs[2][2][256];     // [buf][chain][j]
    __shared__ float part[128 * 33];       // [j][gate*4 + s], row stride 33

    int tid = threadIdx.x;
    int v = blockIdx.x >> 1;
    int r = blockIdx.x & 1;                // == cluster rank
    int j = tid & 127, s = tid >> 7;       // s in [0,4): d-range [s*64, s*64+64)
    int jglob = r * 128 + j;

    // zero h buffers
    for (int i = tid; i < 1024; i += 512) ((float*)hbufs)[i] = 0.0f;
    __syncthreads();
    asm volatile("barrier.cluster.arrive.aligned;" ::: "memory");
    asm volatile("barrier.cluster.wait.aligned;"   ::: "memory");

    const float* x0 = xgv + (size_t)v * 256 * 1024;
    const float* x1 = xgg + (size_t)v * 256 * 1024;
    const float4* pw = pk + (size_t)(s * 64) * 256 + jglob;

    // finisher state
    int fj = tid & 127, fch = tid >> 7;    // valid when tid < 256
    int fjg = r * 128 + fj;
    float cst = 0.0f;

    for (int t = 0; t < 256; t++) {
        int cur = t & 1, nxt = cur ^ 1;

        // prefetch x-gates for finisher threads
        float xi = 0.f, xf = 0.f, xg_ = 0.f, xo = 0.f;
        if (tid < 256) {
            const float* xp = (fch ? x1 : x0) + (size_t)t * 1024 + fjg;
            xi = xp[0]; xf = xp[256]; xg_ = xp[512]; xo = xp[768];
        }

        // partial gate accumulation over d in [s*64, s*64+64)
        float a0 = 0.f, a1 = 0.f, a2 = 0.f, a3 = 0.f;   // chain 0: i,f,g,o
        float a4 = 0.f, a5 = 0.f, a6 = 0.f, a7 = 0.f;   // chain 1
        const float* hc0 = hbufs[cur][0] + s * 64;
        const float* hc1 = hbufs[cur][1] + s * 64;
        for (int dd0 = 0; dd0 < 64; dd0 += 8) {
            float4 w[8]; float h0[8], h1[8];
#pragma unroll
            for (int i = 0; i < 8; i++) w[i] = pw[(size_t)(dd0 + i) * 256];
#pragma unroll
            for (int i = 0; i < 8; i++) { h0[i] = hc0[dd0 + i]; h1[i] = hc1[dd0 + i]; }
#pragma unroll
            for (int i = 0; i < 8; i++) {
                a0 += w[i].x * h0[i]; a1 += w[i].y * h0[i];
                a2 += w[i].z * h0[i]; a3 += w[i].w * h0[i];
                a4 += w[i].x * h1[i]; a5 += w[i].y * h1[i];
                a6 += w[i].z * h1[i]; a7 += w[i].w * h1[i];
            }
        }
        float* pr = part + j * 33 + s;
        pr[0]  = a0; pr[4]  = a1; pr[8]  = a2; pr[12] = a3;
        pr[16] = a4; pr[20] = a5; pr[24] = a6; pr[28] = a7;
        __syncthreads();

        if (tid < 256) {
            const float* q = part + fj * 33 + fch * 16;
            float gi = xi  + q[0]  + q[1]  + q[2]  + q[3];
            float gf = xf  + q[4]  + q[5]  + q[6]  + q[7];
            float gg = xg_ + q[8]  + q[9]  + q[10] + q[11];
            float go = xo  + q[12] + q[13] + q[14] + q[15];
            cst = sigf(gf) * cst + sigf(gi) * tanhf(gg);
            float h = sigf(go) * tanhf(cst);
            // local write
            hbufs[nxt][fch][fjg] = h;
            // remote write (peer CTA)
            uint32_t la = (uint32_t)__cvta_generic_to_shared(&hbufs[nxt][fch][fjg]);
            uint32_t ra;
            asm("mapa.shared::cluster.u32 %0, %1, %2;" : "=r"(ra) : "r"(la), "r"(r ^ 1));
            asm volatile("st.shared::cluster.f32 [%0], %1;" :: "r"(ra), "f"(h) : "memory");
            if (t == 255) hout[(fch * VV + v) * 256 + fjg] = h;
        }
        asm volatile("barrier.cluster.arrive.aligned;" ::: "memory");
        asm volatile("barrier.cluster.wait.aligned;"   ::: "memory");
    }
}

// ---------------- logits + softmax over 2 classes ----------------
__global__ void k_logits(const float* __restrict__ h2, const float* __restrict__ cow,
                         const float* __restrict__ cob, float* __restrict__ probs) {
    int t = blockIdx.x * blockDim.x + threadIdx.x;
    if (t >= 100) return;
    const float* hr = h2 + (size_t)t * 1024;
    float l0 = cob[0], l1 = cob[1];
    for (int d = 0; d < 1024; d++) { l0 += hr[d] * cow[d]; l1 += hr[d] * cow[1024 + d]; }
    float m = fmaxf(l0, l1);
    float e0 = expf(l0 - m), e1 = expf(l1 - m);
    float s = e0 + e1;
    probs[t * 2 + 0] = e0 / s;
    probs[t * 2 + 1] = e1 / s;
}

// ---------------- output assembly: first 52224 floats ----------------
__global__ void k_out(const float* __restrict__ probs, float* __restrict__ out) {
    int i = blockIdx.x * 256 + threadIdx.x;
    if (i >= 52224) return;
    float val;
    if (i < 25600) {                       // res [B,V,2]
        int v = (i >> 1) % 50;
        val = probs[v * 2 + (i & 1)];
    } else if (i < 51200) {                // resg [B,V,2]
        int j = i - 25600;
        int v = (j >> 1) % 50;
        val = probs[(50 + v) * 2 + (j & 1)];
    } else if (i < 51712) {                // res[:, -1]
        val = probs[98 + (i & 1)];
    } else {                               // resg[:, -1]
        val = probs[198 + (i & 1)];
    }
    out[i] = val;
}

// ---------------- host launcher ----------------
extern "C" void kernel_launch(void* const* d_in, const int* in_sizes, int n_in,
                              void* d_out, int out_size) {
    (void)in_sizes; (void)n_in; (void)out_size;
    const int*   seqs = (const int*)  d_in[0];
    const float* st   = (const float*)d_in[1];
    const int*   dt   = (const int*)  d_in[2];
    const float* nn   = (const float*)d_in[3];
    const float* pn   = (const float*)d_in[4];
    const float* emb  = (const float*)d_in[5];
    const float* betas= (const float*)d_in[6];
    const float* tlw  = (const float*)d_in[7];
    const float* tlb  = (const float*)d_in[8];
    const float* tuw  = (const float*)d_in[9];
    const float* tub  = (const float*)d_in[10];
    const float* ipw  = (const float*)d_in[11];
    const float* ipb  = (const float*)d_in[12];
    const float* opw  = (const float*)d_in[13];
    const float* opb  = (const float*)d_in[14];
    const float* wih  = (const float*)d_in[15];
    const float* whh  = (const float*)d_in[16];
    const float* bih  = (const float*)d_in[17];
    const float* bhh  = (const float*)d_in[18];
    const float* c1w  = (const float*)d_in[19];
    const float* c1b  = (const float*)d_in[20];
    const float* c2w  = (const float*)d_in[21];
    const float* c2b  = (const float*)d_in[22];
    const float* cow  = (const float*)d_in[23];
    const float* cob  = (const float*)d_in[24];
    float* out = (float*)d_out;

    float* buf = nullptr;
    cudaGetSymbolAddress((void**)&buf, g_buf);
    float* ab   = buf + OFF_AB;
    float* sa   = buf + OFF_SA;
    float* sb   = buf + OFF_SB;
    float* qp0  = buf + OFF_QP0;
    float* cf   = buf + OFF_CF;
    float* bsum = buf + OFF_BSUM;
    float* b2   = buf + OFF_B2;
    float* Mf   = buf + OFF_MF;
    float* wot  = buf + OFF_WOT;
    float* W2   = buf + OFF_W2;
    float4* pk  = (float4*)(buf + OFF_PK);
    float* hid  = buf + OFF_HID;
    float* ve   = buf + OFF_VE;
    float* g1   = buf + OFF_G1;
    float* kp   = buf + OFF_KP;
    float* vp   = buf + OFF_VP;
    float* O    = buf + OFF_O;
    float* xgv  = buf + OFF_XGV;
    float* xgg  = buf + OFF_XGG;
    float* H    = buf + OFF_H;
    float* H1   = buf + OFF_H1;
    float* H2   = buf + OFF_H2;
    float* prob = buf + OFF_PROB;

    cudaFuncSetAttribute(k_attn, cudaFuncAttributeMaxDynamicSharedMemorySize, ATTN_SHM_BYTES);

    // --- prep ---
    k_ab<<<1, 32>>>(betas, ab);
    k_sab<<<1, 256>>>(dt, ab, sa, sb);
    k_prep<<<6, 256>>>(wih, bih, bhh, ipw, ipb, opb, bsum, b2, cf, qp0);
    k_two<<<256, 256>>>(opw, wot);
    gemm_nt<<<dim3(4, 4),  256>>>(ipw, wot, nullptr, Mf, 256, 256, 256, 0);   // Mf = Wq@Wo
    gemm_nt<<<dim3(4, 16), 256>>>(wih, wot, nullptr, W2, 1024, 256, 256, 0);  // W2 = w_ih@Wo
    k_pack<<<256, 256>>>(whh, pk);

    // --- ve / gen1 ---
    k_hid<<<3200, 256>>>(st, tlw, tlb, hid);
    gemm_nt<<<dim3(4, 200), 256>>>(hid, tuw, tub, ve, 12800, 256, 64, 0);     // tenc -> ve
    k_ve<<<12800, 256>>>(seqs, emb, nn, pn, sa, sb, ve, g1);

    // --- K/V projections of gen1 ---
    gemm_nt<<<dim3(4, 200), 256>>>(g1, ipw + 256 * 256, ipb + 256, kp, 12800, 256, 256, 0);
    gemm_nt<<<dim3(4, 200), 256>>>(g1, ipw + 512 * 256, ipb + 512, vp, 12800, 256, 256, 0);

    // --- LSTM gate pre-activations for the ve branch ---
    gemm_nt<<<dim3(16, 200), 256>>>(ve, wih, bsum, xgv, 12800, 1024, 256, 0);

    // --- 50 serial attention steps ---
    for (int s = 0; s < VV; s++)
        k_attn<<<dim3(8, 16), 256, ATTN_SHM_BYTES>>>(s, kp, vp, O, Mf, cf, qp0);

    // --- LSTM gate pre-activations for the gen branch (Wo folded into W2) ---
    gemm_nt<<<dim3(16, 200), 256>>>(O, W2, b2, xgg, 12800, 1024, 256, 0);

    // --- LSTMs: 50 clusters x 2 CTAs, gate-split across the cluster ---
    k_lstm<<<100, 512>>>(xgv, xgg, pk, H);

    // --- classifier ---
    gemm_nt<<<dim3(16, 2), 256>>>(H,  c1w, c1b, H1, 100, 1024, 256, 1);
    gemm_nt<<<dim3(16, 2), 256>>>(H1, c2w, c2b, H2, 100, 1024, 1024, 1);
    k_logits<<<1, 128>>>(H2, cow, cob, prob);

    // --- outputs ---
    k_out<<<204, 256>>>(prob, out);
    cudaMemcpyAsync(out + 52224,           nn, (size_t)BB * VV * DD * sizeof(float),
                    cudaMemcpyDeviceToDevice);
    cudaMemcpyAsync(out + 52224 + 3276800, pn, (size_t)BB * VV * DD * sizeof(float),
                    cudaMemcpyDeviceToDevice);
}